// round 8
// baseline (speedup 1.0000x reference)
#include <cuda_runtime.h>
#include <cuda_fp16.h>
#include <cstdint>
#include <math.h>

#define BATCH 256
#define SEQ   512
#define DIM   1024
#define VOCAB 32003

// ---------------- scratch (static device globals; no allocation) ----------------
__device__ float g_gi[BATCH * 3 * DIM];
__device__ float g_h0[BATCH * DIM];
__device__ float g_cat[BATCH * 2 * DIM];
__device__ float g_preK[2][BATCH * DIM];          // split-K partials of preout
__device__ uint32_t g_Apack[BATCH * (DIM / 2)];   // pre-swizzled fp16 A for logits

// ---------------- packed fp32x2 helpers (FFMA2) ----------------
__device__ __forceinline__ unsigned long long dup2(float x) {
    unsigned long long r;
    asm("mov.b64 %0, {%1, %1};" : "=l"(r) : "r"(__float_as_uint(x)));
    return r;
}
__device__ __forceinline__ void fma2(unsigned long long& d, unsigned long long a, unsigned long long b) {
    asm("fma.rn.f32x2 %0, %1, %2, %0;" : "+l"(d) : "l"(a), "l"(b));
}
union F2U { unsigned long long u; float2 f; };

__device__ __forceinline__ float celu1(float x) { return x > 0.f ? x : expm1f(x); }

// ---------------- fp16 helpers ----------------
__device__ __forceinline__ uint32_t h2pack(float x, float y) {
    __half2 h = __floats2half2_rn(x, y);
    return *(uint32_t*)&h;
}
__device__ __forceinline__ uint4 packq(float4 x, float4 y) {
    uint4 w;
    w.x = h2pack(x.x, x.y);
    w.y = h2pack(y.x, y.y);
    w.z = h2pack(x.z, x.w);
    w.w = h2pack(y.z, y.w);
    return w;
}
__device__ __forceinline__ void mmaf16(float* c, uint32_t a0, uint32_t a1, uint32_t a2,
                                       uint32_t a3, uint32_t b0, uint32_t b1) {
    asm volatile("mma.sync.aligned.m16n8k16.row.col.f32.f16.f16.f32 "
                 "{%0,%1,%2,%3}, {%4,%5,%6,%7}, {%8,%9}, {%0,%1,%2,%3};"
                 : "+f"(c[0]), "+f"(c[1]), "+f"(c[2]), "+f"(c[3])
                 : "r"(a0), "r"(a1), "r"(a2), "r"(a3), "r"(b0), "r"(b1));
}

// ---------------- cp.async helpers ----------------
#define CP_ASYNC16(dst, src) \
    asm volatile("cp.async.cg.shared.global [%0], [%1], 16;" :: "r"(dst), "l"(src))
#define CP_COMMIT() asm volatile("cp.async.commit_group;" ::: "memory")
#define CP_WAIT0()  asm volatile("cp.async.wait_group 0;" ::: "memory")
#define CP_WAIT1()  asm volatile("cp.async.wait_group 1;" ::: "memory")

// =====================================================================
// gemmT: C[256, N] = A[256, K-slice] @ B[N, K-slice]^T (+ bias)
// FFMA2, dup-free inner loop. Tile 128x64, 256 threads, thread = 8m x 4n.
// As k-major/m-contiguous (f32x2 = (m, m+1)); Bs pre-duplicated u64.
// Double-buffered, 16-k chunks. gridDim.z = K-split (A,B advance z*K;
// C advances z*czstride). gather = optional A row indices.
// =====================================================================
__global__ void __launch_bounds__(256)
gemmT(int N, int K,
      const float* __restrict__ A, int lda,
      const float* __restrict__ B, int ldb,
      float* __restrict__ C, int ldc,
      const float* __restrict__ bias,
      const int* __restrict__ gather,
      size_t czstride)
{
    __shared__ float As[2][16][132];
    __shared__ unsigned long long Bs[2][16][66];

    const int t  = threadIdx.x;
    const int gn = blockIdx.x;
    const int gm = blockIdx.y;
    const int koff = blockIdx.z * K;
    A += koff;
    B += koff;
    C += (size_t)blockIdx.z * czstride;

    // ---- producer setup ----
    const int am  = t >> 1;            // A row in tile 0..127
    const int akh = (t & 1) * 8;       // k-half within chunk
    int arow = gm * 128 + am;
    if (gather) arow = gather[arow];
    const float* asrc = A + (size_t)arow * lda + akh;

    const int bn  = t >> 2;            // B row in tile 0..63
    const int bkq = (t & 3) * 4;       // k-quarter
    const float* bsrc = B + (size_t)(gn * 64 + bn) * ldb + bkq;

    float4 av0, av1, bv;
    auto ldAB = [&](int ch) {
        const float4* pa = (const float4*)(asrc + ch * 16);
        av0 = pa[0];
        av1 = pa[1];
        bv = *(const float4*)(bsrc + ch * 16);
    };
    auto stAB = [&](int buf) {
        As[buf][akh + 0][am] = av0.x;
        As[buf][akh + 1][am] = av0.y;
        As[buf][akh + 2][am] = av0.z;
        As[buf][akh + 3][am] = av0.w;
        As[buf][akh + 4][am] = av1.x;
        As[buf][akh + 5][am] = av1.y;
        As[buf][akh + 6][am] = av1.z;
        As[buf][akh + 7][am] = av1.w;
        Bs[buf][bkq + 0][bn] = dup2(bv.x);
        Bs[buf][bkq + 1][bn] = dup2(bv.y);
        Bs[buf][bkq + 2][bn] = dup2(bv.z);
        Bs[buf][bkq + 3][bn] = dup2(bv.w);
    };

    // ---- consumer setup ----
    const int tx = t & 15;    // m group: rows tx*8 .. tx*8+7
    const int ty = t >> 4;    // n group: cols ty*4 .. ty*4+3

    unsigned long long acc[4][4];
#pragma unroll
    for (int i = 0; i < 4; i++)
#pragma unroll
        for (int j = 0; j < 4; j++) acc[i][j] = 0ULL;

    const int NCH = K / 16;
    ldAB(0);
    stAB(0);
    ldAB(1);
    __syncthreads();

    for (int ch = 0; ch < NCH; ch++) {
        if (ch + 1 < NCH) stAB((ch + 1) & 1);
        if (ch + 2 < NCH) ldAB(ch + 2);

        const int buf = ch & 1;
#pragma unroll
        for (int k = 0; k < 16; k++) {
            const float* Ak = &As[buf][k][tx * 8];
            ulonglong2 A0 = *(const ulonglong2*)Ak;
            ulonglong2 A1 = *(const ulonglong2*)(Ak + 4);
            ulonglong2 B0 = *(const ulonglong2*)&Bs[buf][k][ty * 4];
            ulonglong2 B1 = *(const ulonglong2*)&Bs[buf][k][ty * 4 + 2];
            unsigned long long aa[4] = {A0.x, A0.y, A1.x, A1.y};
            unsigned long long bb[4] = {B0.x, B0.y, B1.x, B1.y};
#pragma unroll
            for (int i = 0; i < 4; i++)
#pragma unroll
                for (int j = 0; j < 4; j++) fma2(acc[i][j], aa[i], bb[j]);
        }
        __syncthreads();
    }

    // ---- epilogue ----
    const int mg = gm * 128 + tx * 8;
    const int ng = gn * 64 + ty * 4;
    float bz[4];
#pragma unroll
    for (int j = 0; j < 4; j++) bz[j] = bias ? bias[ng + j] : 0.f;
#pragma unroll
    for (int i = 0; i < 4; i++) {
        float* r0 = C + (size_t)(mg + 2 * i) * ldc + ng;
        float* r1 = r0 + ldc;
#pragma unroll
        for (int j = 0; j < 4; j++) {
            F2U v; v.u = acc[i][j];
            r0[j] = v.f.x + bz[j];
            r1[j] = v.f.y + bz[j];
        }
    }
}

// =====================================================================
// Combine preout split-K partials + bias + celu, then pack into the
// swizzled fp16 layout for the logits GEMM A operand.
// =====================================================================
__global__ void __launch_bounds__(256)
prepack_combine(const float* __restrict__ P0, const float* __restrict__ P1,
                const float* __restrict__ bias, uint32_t* __restrict__ out)
{
    int idx = blockIdx.x * 256 + threadIdx.x;     // 8192 = 256 rows x 32 chunks
    int row = idx >> 5, ch = idx & 31;
    const float4* a0 = (const float4*)(P0 + (size_t)row * DIM + ch * 32);
    const float4* a1 = (const float4*)(P1 + (size_t)row * DIM + ch * 32);
    const float4* bb = (const float4*)(bias + ch * 32);
    float4 q[8];
#pragma unroll
    for (int i = 0; i < 8; i++) {
        float4 x = a0[i], y = a1[i], b = bb[i];
        q[i].x = celu1(x.x + y.x + b.x);
        q[i].y = celu1(x.y + y.y + b.y);
        q[i].z = celu1(x.z + y.z + b.z);
        q[i].w = celu1(x.w + y.w + b.w);
    }
    int bp = (row >> 2) & 1;
    uint32_t* o = out + (size_t)row * (DIM / 2) + ch * 16;
    *(uint4*)(o + 4 * bp)           = packq(q[0], q[2]);
    *(uint4*)(o + 4 * (bp ^ 1))     = packq(q[1], q[3]);
    *(uint4*)(o + 8 + 4 * (bp ^ 1)) = packq(q[4], q[6]);
    *(uint4*)(o + 8 + 4 * bp)       = packq(q[5], q[7]);
}

// =====================================================================
// Logits GEMM: C[256, 32003] = A[256,1024] @ B[32003,1024]^T + bias
// fp16 mma.sync. CTA tile 128x128, 8 warps (2x4), warp tile 64x32, K=32/chunk.
// A plane via cp.async from g_Apack (pre-swizzled); B converted 2 thr/row.
// =====================================================================
#define LP    24
#define PLANE (128 * LP)
#define BUFW  (2 * PLANE)
#define LG_SMEM_BYTES (2 * BUFW * 4)   // 49152

__global__ void __launch_bounds__(256, 2)
logits_f16(const uint32_t* __restrict__ Apack, const float* __restrict__ Bw,
           const float* __restrict__ bias, float* __restrict__ C)
{
    extern __shared__ uint32_t sm[];
    const uint32_t smb = (uint32_t)__cvta_generic_to_shared(sm);
    const int t    = threadIdx.x;
    const int lane = t & 31;
    const int wid  = t >> 5;
    const int wm   = wid >> 2;
    const int wn   = wid & 3;
    const int bm   = blockIdx.x & 1;
    const int bn   = blockIdx.x >> 1;

    const int rb   = t >> 1;
    const int half = t & 1;
    const int bpB  = (rb >> 2) & 1;
    int ng = bn * 128 + rb;
    if (ng > VOCAB - 1) ng = VOCAB - 1;
    const float* gsrcB = Bw + (size_t)ng * DIM + half * 16;
    const int wq0 = 8 * half + 4 * (bpB ^ half);
    const int wq1 = 8 * half + 4 * ((bpB ^ 1) ^ half);
    const uint32_t* srcA = Apack + (size_t)(bm * 128 + rb) * (DIM / 2) + half * 8;
    const uint32_t dstA_row = (uint32_t)(rb * LP + half * 8) * 4;

    float4 pf[4];
    auto ldB = [&](int ch) {
        const float4* p = (const float4*)(gsrcB + ch * 32);
        pf[0] = p[0]; pf[1] = p[1]; pf[2] = p[2]; pf[3] = p[3];
    };
    auto stB = [&](int buf) {
        uint32_t* base = sm + buf * BUFW + PLANE + rb * LP;
        *(uint4*)(base + wq0) = packq(pf[0], pf[2]);
        *(uint4*)(base + wq1) = packq(pf[1], pf[3]);
    };
    auto issueA = [&](int ch, int buf) {
        uint32_t d = smb + (uint32_t)buf * BUFW * 4 + dstA_row;
        const uint32_t* s = srcA + ch * 16;
        CP_ASYNC16(d, s);
        CP_ASYNC16(d + 16, s + 4);
    };

    float acc[4][4][4];
#pragma unroll
    for (int i = 0; i < 4; i++)
#pragma unroll
        for (int j = 0; j < 4; j++)
#pragma unroll
            for (int k = 0; k < 4; k++) acc[i][j][k] = 0.f;

    const int c_ = lane & 3;
    const int bt = (lane >> 4) & 1;
    const int q2 = (c_ >> 1) ^ bt;
    const int rA = wm * 64 + (lane >> 2);
    const int cB = wn * 32 + (lane >> 2);

    issueA(0, 0); CP_COMMIT();
    ldB(0); stB(0);
    ldB(1);
    CP_WAIT0();
    __syncthreads();

    const int NCHUNK = DIM / 32;
    for (int ch = 0; ch < NCHUNK; ch++) {
        const int wb = (ch + 1) & 1;
        if (ch + 1 < NCHUNK) {
            issueA(ch + 1, wb); CP_COMMIT();
            stB(wb);
        }
        if (ch + 2 < NCHUNK) ldB(ch + 2);

        const uint32_t* Ab = sm + (ch & 1) * BUFW;
        const uint32_t* Bb = Ab + PLANE;
#pragma unroll
        for (int h = 0; h < 2; h++) {
            const int off = 8 * h + 4 * (q2 ^ h) + 2 * (c_ & 1);
            uint2 af[4][2];
#pragma unroll
            for (int mt = 0; mt < 4; mt++) {
                af[mt][0] = *(const uint2*)(Ab + (rA + 16 * mt) * LP + off);
                af[mt][1] = *(const uint2*)(Ab + (rA + 16 * mt + 8) * LP + off);
            }
#pragma unroll
            for (int nt = 0; nt < 4; nt++) {
                uint2 bf = *(const uint2*)(Bb + (cB + 8 * nt) * LP + off);
#pragma unroll
                for (int mt = 0; mt < 4; mt++)
                    mmaf16(acc[mt][nt], af[mt][0].x, af[mt][1].x,
                           af[mt][0].y, af[mt][1].y, bf.x, bf.y);
            }
        }
        if (ch + 1 < NCHUNK) CP_WAIT0();
        __syncthreads();
    }

    const int n0 = bn * 128 + wn * 32 + 2 * c_;
    float bz[8];
#pragma unroll
    for (int nt = 0; nt < 4; nt++) {
        int n = n0 + 8 * nt;
        bz[2 * nt]     = (n     < VOCAB) ? bias[n]     : 0.f;
        bz[2 * nt + 1] = (n + 1 < VOCAB) ? bias[n + 1] : 0.f;
    }
    const int m0 = bm * 128 + wm * 64 + (lane >> 2);
#pragma unroll
    for (int mt = 0; mt < 4; mt++) {
        float* r0 = C + (size_t)(m0 + 16 * mt) * VOCAB;
        float* r1 = r0 + (size_t)8 * VOCAB;
#pragma unroll
        for (int nt = 0; nt < 4; nt++) {
            int n = n0 + 8 * nt;
            if (n < VOCAB) {
                r0[n] = acc[mt][nt][0] + bz[2 * nt];
                r1[n] = acc[mt][nt][2] + bz[2 * nt];
            }
            if (n + 1 < VOCAB) {
                r0[n + 1] = acc[mt][nt][1] + bz[2 * nt + 1];
                r1[n + 1] = acc[mt][nt][3] + bz[2 * nt + 1];
            }
        }
    }
}

// =====================================================================
// GRU gates (zero previous hidden state): h' = (1-z) * n   (layer 0)
// =====================================================================
__global__ void gru_gates(const float* __restrict__ gi, const float* __restrict__ bhh,
                          float* __restrict__ h, int ldh)
{
    int idx = blockIdx.x * blockDim.x + threadIdx.x;
    int b = idx >> 10, d = idx & 1023;
    const float* g = gi + (size_t)b * (3 * DIM);
    float r = 1.f / (1.f + expf(-(g[d]           + bhh[d])));
    float z = 1.f / (1.f + expf(-(g[DIM + d]     + bhh[DIM + d])));
    float n = tanhf(g[2 * DIM + d] + r * bhh[2 * DIM + d]);
    h[(size_t)b * ldh + d] = (1.f - z) * n;
}

// =====================================================================
// Fused attention: h1 gates in-block + online-softmax summary.
// cp.async double-buffered enc tiles; mask preloaded to smem.
// =====================================================================
#define ATTN_SMEM_BYTES ((1024 + 2 * 8 * 1024 + 8 + 512) * 4)

__global__ void __launch_bounds__(256)
attn_kernel(const float* __restrict__ enc, const int* __restrict__ mask,
            const float* __restrict__ gi, const float* __restrict__ bhh,
            float* __restrict__ cat)
{
    extern __shared__ float smf[];
    float* h1s   = smf;
    float* tiles = smf + 1024;
    float* wsh   = smf + 1024 + 16384;
    int*   msk   = (int*)(smf + 1024 + 16384 + 8);

    const int b   = blockIdx.x;
    const int tid = threadIdx.x;
    const float* encb  = enc  + (size_t)b * SEQ * DIM;
    const int*   maskb = mask + b * SEQ;

    msk[tid]       = maskb[tid];
    msk[tid + 256] = maskb[tid + 256];

    {
        const float* g = gi + (size_t)b * (3 * DIM);
        int d = tid * 4;
        float4 vr = *(const float4*)(g + d);
        float4 vz = *(const float4*)(g + DIM + d);
        float4 vn = *(const float4*)(g + 2 * DIM + d);
        float4 br = *(const float4*)(bhh + d);
        float4 bz = *(const float4*)(bhh + DIM + d);
        float4 bn = *(const float4*)(bhh + 2 * DIM + d);
        float h[4];
        float r0 = 1.f / (1.f + expf(-(vr.x + br.x)));
        float z0 = 1.f / (1.f + expf(-(vz.x + bz.x)));
        h[0] = (1.f - z0) * tanhf(vn.x + r0 * bn.x);
        float r1 = 1.f / (1.f + expf(-(vr.y + br.y)));
        float z1 = 1.f / (1.f + expf(-(vz.y + bz.y)));
        h[1] = (1.f - z1) * tanhf(vn.y + r1 * bn.y);
        float r2 = 1.f / (1.f + expf(-(vr.z + br.z)));
        float z2 = 1.f / (1.f + expf(-(vz.z + bz.z)));
        h[2] = (1.f - z2) * tanhf(vn.z + r2 * bn.z);
        float r3 = 1.f / (1.f + expf(-(vr.w + br.w)));
        float z3 = 1.f / (1.f + expf(-(vz.w + bz.w)));
        h[3] = (1.f - z3) * tanhf(vn.w + r3 * bn.w);
        float4 hv = make_float4(h[0], h[1], h[2], h[3]);
        *(float4*)(h1s + d) = hv;
        *(float4*)(cat + (size_t)b * (2 * DIM) + d) = hv;
    }

    const uint32_t tbase = (uint32_t)__cvta_generic_to_shared(tiles);
    auto issue = [&](int it) {
        const float* src = encb + (size_t)it * 8 * DIM + tid * 4;
        uint32_t dst = tbase + (uint32_t)((it & 1) * 32768 + tid * 16);
#pragma unroll
        for (int i = 0; i < 8; i++)
            CP_ASYNC16(dst + i * 4096, (const void*)(src + i * 1024));
    };

    issue(0); CP_COMMIT();
    issue(1); CP_COMMIT();

    float m = -1e30f, l = 0.f;
    float4 acc = make_float4(0.f, 0.f, 0.f, 0.f);

    for (int it = 0; it < SEQ / 8; it++) {
        CP_WAIT1();
        __syncthreads();
        const float* tb = tiles + (it & 1) * 8192;

        {
            int w = tid >> 5, lane = tid & 31;
            float p = 0.f;
            const float4* er = (const float4*)(tb + w * 1024);
            const float4* hr = (const float4*)h1s;
#pragma unroll
            for (int i = 0; i < 8; i++) {
                float4 e  = er[lane + i * 32];
                float4 hv = hr[lane + i * 32];
                p += e.x * hv.x + e.y * hv.y + e.z * hv.z + e.w * hv.w;
            }
#pragma unroll
            for (int off = 16; off; off >>= 1) p += __shfl_xor_sync(0xffffffffu, p, off);
            if (lane == 0) wsh[w] = msk[it * 8 + w] ? p : -1e30f;
        }
        __syncthreads();

        float wv[8];
        float tm = -1e30f;
#pragma unroll
        for (int j = 0; j < 8; j++) { wv[j] = wsh[j]; tm = fmaxf(tm, wv[j]); }
        float mnew  = fmaxf(m, tm);
        float scale = __expf(m - mnew);
        l *= scale;
        acc.x *= scale; acc.y *= scale; acc.z *= scale; acc.w *= scale;
#pragma unroll
        for (int j = 0; j < 8; j++) {
            float pj = __expf(wv[j] - mnew);
            l += pj;
            float4 e = *(const float4*)(tb + j * 1024 + tid * 4);
            acc.x += pj * e.x; acc.y += pj * e.y; acc.z += pj * e.z; acc.w += pj * e.w;
        }
        m = mnew;
        __syncthreads();

        if (it + 2 < SEQ / 8) issue(it + 2);
        CP_COMMIT();
    }

    float inv = 1.f / l;
    float4 o = make_float4(acc.x * inv, acc.y * inv, acc.z * inv, acc.w * inv);
    *(float4*)(cat + (size_t)b * (2 * DIM) + DIM + tid * 4) = o;
}

// =====================================================================
// launcher
// =====================================================================
extern "C" void kernel_launch(void* const* d_in, const int* in_sizes, int n_in,
                              void* d_out, int out_size)
{
    (void)in_sizes; (void)n_in; (void)out_size;
    const int*   tokens   = (const int*)  d_in[0];
    const float* enc      = (const float*)d_in[1];
    const int*   encmask  = (const int*)  d_in[2];
    const float* dec_emb  = (const float*)d_in[3];
    const float* Wih0     = (const float*)d_in[4];
    const float* bih0     = (const float*)d_in[6];
    const float* bhh0     = (const float*)d_in[7];
    const float* Wih1     = (const float*)d_in[8];
    const float* bih1     = (const float*)d_in[10];
    const float* bhh1     = (const float*)d_in[11];
    const float* preout_w = (const float*)d_in[12];
    const float* preout_b = (const float*)d_in[13];
    const float* out_w    = (const float*)d_in[14];
    const float* out_b    = (const float*)d_in[15];
    float* logits = (float*)d_out;

    float *gi, *h0, *cat, *preK;
    uint32_t* apack;
    cudaGetSymbolAddress((void**)&gi,    g_gi);
    cudaGetSymbolAddress((void**)&h0,    g_h0);
    cudaGetSymbolAddress((void**)&cat,   g_cat);
    cudaGetSymbolAddress((void**)&preK,  g_preK);
    cudaGetSymbolAddress((void**)&apack, g_Apack);

    static int smem_set = 0;
    if (!smem_set) {
        cudaFuncSetAttribute(logits_f16, cudaFuncAttributeMaxDynamicSharedMemorySize, LG_SMEM_BYTES);
        cudaFuncSetAttribute(attn_kernel, cudaFuncAttributeMaxDynamicSharedMemorySize, ATTN_SMEM_BYTES);
        smem_set = 1;
    }

    // 1) gi0 = dec_emb[tokens] @ Wih0[:, :D]^T + bih0   (gathered A)
    gemmT<<<dim3(3 * DIM / 64, 2, 1), 256>>>(
        3 * DIM, DIM, dec_emb, DIM, Wih0, 2 * DIM, gi, 3 * DIM, bih0, tokens, 0);

    // 2) h0
    gru_gates<<<(BATCH * DIM) / 256, 256>>>(gi, bhh0, h0, DIM);

    // 3) gi1 = h0 @ Wih1^T + bih1
    gemmT<<<dim3(3 * DIM / 64, 2, 1), 256>>>(
        3 * DIM, DIM, h0, DIM, Wih1, DIM, gi, 3 * DIM, bih1, nullptr, 0);

    // 4) fused: h1 gates + attention summary -> cat
    attn_kernel<<<BATCH, 256, ATTN_SMEM_BYTES>>>(enc, encmask, gi, bhh1, cat);

    // 5) preout split-K: preK[z] = cat[:, z*1024:] @ preout_w[:, z*1024:]^T
    gemmT<<<dim3(DIM / 64, 2, 2), 256>>>(
        DIM, DIM, cat, 2 * DIM, preout_w, 2 * DIM, preK, DIM, nullptr, nullptr,
        (size_t)BATCH * DIM);

    // 6) combine + bias + celu + fp16 pack for logits A
    prepack_combine<<<32, 256>>>(preK, preK + (size_t)BATCH * DIM, preout_b, apack);

    // 7) logits = Apack @ out_w^T + out_b   (fp16 mma.sync)
    logits_f16<<<((VOCAB + 127) / 128) * 2, 256, LG_SMEM_BYTES>>>(apack, out_w, out_b, logits);
}

// round 9
// speedup vs baseline: 2.5175x; 2.5175x over previous
#include <cuda_runtime.h>
#include <cuda_fp16.h>
#include <cstdint>
#include <math.h>

#define BATCH 256
#define SEQ   512
#define DIM   1024
#define VOCAB 32003

// ---------------- scratch ----------------
__device__ float g_gi[BATCH * 3 * DIM];
__device__ float g_h0[BATCH * DIM];
__device__ float g_cat[BATCH * 2 * DIM];
__device__ float g_pre[BATCH * DIM];
__device__ uint32_t g_Apack[BATCH * (DIM / 2)];

__device__ __forceinline__ float celu1(float x) { return x > 0.f ? x : expm1f(x); }

// ---------------- fp16 helpers ----------------
__device__ __forceinline__ uint32_t h2pack(float x, float y) {
    __half2 h = __floats2half2_rn(x, y);
    return *(uint32_t*)&h;
}
__device__ __forceinline__ uint4 packq(float4 x, float4 y) {
    uint4 w;
    w.x = h2pack(x.x, x.y);
    w.y = h2pack(y.x, y.y);
    w.z = h2pack(x.z, x.w);
    w.w = h2pack(y.z, y.w);
    return w;
}
__device__ __forceinline__ void mmaf16(float* c, uint32_t a0, uint32_t a1, uint32_t a2,
                                       uint32_t a3, uint32_t b0, uint32_t b1) {
    asm volatile("mma.sync.aligned.m16n8k16.row.col.f32.f16.f16.f32 "
                 "{%0,%1,%2,%3}, {%4,%5,%6,%7}, {%8,%9}, {%0,%1,%2,%3};"
                 : "+f"(c[0]), "+f"(c[1]), "+f"(c[2]), "+f"(c[3])
                 : "r"(a0), "r"(a1), "r"(a2), "r"(a3), "r"(b0), "r"(b1));
}

// ---------------- cp.async helpers ----------------
#define CP_ASYNC16(dst, src) \
    asm volatile("cp.async.cg.shared.global [%0], [%1], 16;" :: "r"(dst), "l"(src))
#define CP_COMMIT() asm volatile("cp.async.commit_group;" ::: "memory")
#define CP_WAIT0()  asm volatile("cp.async.wait_group 0;" ::: "memory")
#define CP_WAIT1()  asm volatile("cp.async.wait_group 1;" ::: "memory")

#define LP    24
#define PLANE (128 * LP)
#define BUFW  (2 * PLANE)
#define LG_SMEM_BYTES (2 * BUFW * 4)   // 49152

// =====================================================================
// Generic fp16 MMA GEMM: C[M=256, N] = A[256,K] @ B[N,K]^T + bias (opt celu)
// Same proven layout as logits_f16: pitch-24, half/quad XOR swizzle,
// CTA tile 128x128, 8 warps, warp 64x32. Both A and B converted fp32->fp16
// by producers (2 threads per smem row). N, K multiples of 128/32; no guards.
// grid.x = 2 * (N/128): bm = x&1, bn = x>>1.
// =====================================================================
template<int ACT>
__global__ void __launch_bounds__(256)
gemm_f16(int N, int K,
         const float* __restrict__ A, int lda, const int* __restrict__ gather,
         const float* __restrict__ Bw, int ldb,
         const float* __restrict__ bias,
         float* __restrict__ C, int ldc)
{
    extern __shared__ uint32_t sm[];
    const int t    = threadIdx.x;
    const int lane = t & 31;
    const int wid  = t >> 5;
    const int wm   = wid >> 2;
    const int wn   = wid & 3;
    const int bm   = blockIdx.x & 1;
    const int bn   = blockIdx.x >> 1;

    // ---- producer: thread handles half-row rb of A AND of B ----
    const int rb   = t >> 1;
    const int half = t & 1;
    const int bp   = (rb >> 2) & 1;
    const int wq0  = 8 * half + 4 * (bp ^ half);
    const int wq1  = 8 * half + 4 * ((bp ^ 1) ^ half);

    int arow = bm * 128 + rb;
    if (gather) arow = gather[arow];
    const float* asrc = A + (size_t)arow * lda + half * 16;
    const float* bsrc = Bw + (size_t)(bn * 128 + rb) * ldb + half * 16;

    float4 pa[4], pb[4];
    auto ldAB = [&](int ch) {
        const float4* qa = (const float4*)(asrc + ch * 32);
        pa[0] = qa[0]; pa[1] = qa[1]; pa[2] = qa[2]; pa[3] = qa[3];
        const float4* qb = (const float4*)(bsrc + ch * 32);
        pb[0] = qb[0]; pb[1] = qb[1]; pb[2] = qb[2]; pb[3] = qb[3];
    };
    auto stAB = [&](int buf) {
        uint32_t* ba = sm + buf * BUFW + rb * LP;
        *(uint4*)(ba + wq0) = packq(pa[0], pa[2]);
        *(uint4*)(ba + wq1) = packq(pa[1], pa[3]);
        uint32_t* bbp = ba + PLANE;
        *(uint4*)(bbp + wq0) = packq(pb[0], pb[2]);
        *(uint4*)(bbp + wq1) = packq(pb[1], pb[3]);
    };

    float acc[4][4][4];
#pragma unroll
    for (int i = 0; i < 4; i++)
#pragma unroll
        for (int j = 0; j < 4; j++)
#pragma unroll
            for (int k = 0; k < 4; k++) acc[i][j][k] = 0.f;

    const int c_ = lane & 3;
    const int bt = (lane >> 4) & 1;
    const int q2 = (c_ >> 1) ^ bt;
    const int rA = wm * 64 + (lane >> 2);
    const int cB = wn * 32 + (lane >> 2);

    ldAB(0);
    stAB(0);
    ldAB(1);
    __syncthreads();

    const int NCHUNK = K / 32;
    for (int ch = 0; ch < NCHUNK; ch++) {
        if (ch + 1 < NCHUNK) stAB((ch + 1) & 1);
        if (ch + 2 < NCHUNK) ldAB(ch + 2);

        const uint32_t* Ab = sm + (ch & 1) * BUFW;
        const uint32_t* Bb = Ab + PLANE;
#pragma unroll
        for (int h = 0; h < 2; h++) {
            const int off = 8 * h + 4 * (q2 ^ h) + 2 * (c_ & 1);
            uint2 af[4][2];
#pragma unroll
            for (int mt = 0; mt < 4; mt++) {
                af[mt][0] = *(const uint2*)(Ab + (rA + 16 * mt) * LP + off);
                af[mt][1] = *(const uint2*)(Ab + (rA + 16 * mt + 8) * LP + off);
            }
#pragma unroll
            for (int nt = 0; nt < 4; nt++) {
                uint2 bf = *(const uint2*)(Bb + (cB + 8 * nt) * LP + off);
#pragma unroll
                for (int mt = 0; mt < 4; mt++)
                    mmaf16(acc[mt][nt], af[mt][0].x, af[mt][1].x,
                           af[mt][0].y, af[mt][1].y, bf.x, bf.y);
            }
        }
        __syncthreads();
    }

    // epilogue (unguarded: N multiple of 128)
    const int n0 = bn * 128 + wn * 32 + 2 * c_;
    float bz[8];
#pragma unroll
    for (int nt = 0; nt < 4; nt++) {
        bz[2 * nt]     = bias[n0 + 8 * nt];
        bz[2 * nt + 1] = bias[n0 + 8 * nt + 1];
    }
    const int m0 = bm * 128 + wm * 64 + (lane >> 2);
#pragma unroll
    for (int mt = 0; mt < 4; mt++) {
        float* r0 = C + (size_t)(m0 + 16 * mt) * ldc;
        float* r1 = r0 + (size_t)8 * ldc;
#pragma unroll
        for (int nt = 0; nt < 4; nt++) {
            int n = n0 + 8 * nt;
            float v0 = acc[mt][nt][0] + bz[2 * nt];
            float v1 = acc[mt][nt][1] + bz[2 * nt + 1];
            float v2 = acc[mt][nt][2] + bz[2 * nt];
            float v3 = acc[mt][nt][3] + bz[2 * nt + 1];
            if (ACT) { v0 = celu1(v0); v1 = celu1(v1); v2 = celu1(v2); v3 = celu1(v3); }
            r0[n] = v0; r0[n + 1] = v1;
            r1[n] = v2; r1[n + 1] = v3;
        }
    }
}

// =====================================================================
// Pack pre (256x1024 fp32) into swizzled fp16 layout for logits A.
// =====================================================================
__global__ void __launch_bounds__(256)
prepackA(const float* __restrict__ A, uint32_t* __restrict__ out)
{
    int idx = blockIdx.x * 256 + threadIdx.x;
    int row = idx >> 5, ch = idx & 31;
    const float4* p = (const float4*)(A + (size_t)row * DIM + ch * 32);
    float4 p0 = p[0], p1 = p[1], p2 = p[2], p3 = p[3];
    float4 p4 = p[4], p5 = p[5], p6 = p[6], p7 = p[7];
    int bp = (row >> 2) & 1;
    uint32_t* o = out + (size_t)row * (DIM / 2) + ch * 16;
    *(uint4*)(o + 4 * bp)           = packq(p0, p2);
    *(uint4*)(o + 4 * (bp ^ 1))     = packq(p1, p3);
    *(uint4*)(o + 8 + 4 * (bp ^ 1)) = packq(p4, p6);
    *(uint4*)(o + 8 + 4 * bp)       = packq(p5, p7);
}

// =====================================================================
// Logits GEMM (unchanged from R7): fp16 mma.sync, cp.async A, 2 CTAs/SM.
// =====================================================================
__global__ void __launch_bounds__(256, 2)
logits_f16(const uint32_t* __restrict__ Apack, const float* __restrict__ Bw,
           const float* __restrict__ bias, float* __restrict__ C)
{
    extern __shared__ uint32_t sm[];
    const uint32_t smb = (uint32_t)__cvta_generic_to_shared(sm);
    const int t    = threadIdx.x;
    const int lane = t & 31;
    const int wid  = t >> 5;
    const int wm   = wid >> 2;
    const int wn   = wid & 3;
    const int bm   = blockIdx.x & 1;
    const int bn   = blockIdx.x >> 1;

    const int rb   = t >> 1;
    const int half = t & 1;
    const int bpB  = (rb >> 2) & 1;
    int ng = bn * 128 + rb;
    if (ng > VOCAB - 1) ng = VOCAB - 1;
    const float* gsrcB = Bw + (size_t)ng * DIM + half * 16;
    const int wq0 = 8 * half + 4 * (bpB ^ half);
    const int wq1 = 8 * half + 4 * ((bpB ^ 1) ^ half);
    const uint32_t* srcA = Apack + (size_t)(bm * 128 + rb) * (DIM / 2) + half * 8;
    const uint32_t dstA_row = (uint32_t)(rb * LP + half * 8) * 4;

    float4 pf[4];
    auto ldB = [&](int ch) {
        const float4* p = (const float4*)(gsrcB + ch * 32);
        pf[0] = p[0]; pf[1] = p[1]; pf[2] = p[2]; pf[3] = p[3];
    };
    auto stB = [&](int buf) {
        uint32_t* base = sm + buf * BUFW + PLANE + rb * LP;
        *(uint4*)(base + wq0) = packq(pf[0], pf[2]);
        *(uint4*)(base + wq1) = packq(pf[1], pf[3]);
    };
    auto issueA = [&](int ch, int buf) {
        uint32_t d = smb + (uint32_t)buf * BUFW * 4 + dstA_row;
        const uint32_t* s = srcA + ch * 16;
        CP_ASYNC16(d, s);
        CP_ASYNC16(d + 16, s + 4);
    };

    float acc[4][4][4];
#pragma unroll
    for (int i = 0; i < 4; i++)
#pragma unroll
        for (int j = 0; j < 4; j++)
#pragma unroll
            for (int k = 0; k < 4; k++) acc[i][j][k] = 0.f;

    const int c_ = lane & 3;
    const int bt = (lane >> 4) & 1;
    const int q2 = (c_ >> 1) ^ bt;
    const int rA = wm * 64 + (lane >> 2);
    const int cB = wn * 32 + (lane >> 2);

    issueA(0, 0); CP_COMMIT();
    ldB(0); stB(0);
    ldB(1);
    CP_WAIT0();
    __syncthreads();

    const int NCHUNK = DIM / 32;
    for (int ch = 0; ch < NCHUNK; ch++) {
        const int wb = (ch + 1) & 1;
        if (ch + 1 < NCHUNK) {
            issueA(ch + 1, wb); CP_COMMIT();
            stB(wb);
        }
        if (ch + 2 < NCHUNK) ldB(ch + 2);

        const uint32_t* Ab = sm + (ch & 1) * BUFW;
        const uint32_t* Bb = Ab + PLANE;
#pragma unroll
        for (int h = 0; h < 2; h++) {
            const int off = 8 * h + 4 * (q2 ^ h) + 2 * (c_ & 1);
            uint2 af[4][2];
#pragma unroll
            for (int mt = 0; mt < 4; mt++) {
                af[mt][0] = *(const uint2*)(Ab + (rA + 16 * mt) * LP + off);
                af[mt][1] = *(const uint2*)(Ab + (rA + 16 * mt + 8) * LP + off);
            }
#pragma unroll
            for (int nt = 0; nt < 4; nt++) {
                uint2 bf = *(const uint2*)(Bb + (cB + 8 * nt) * LP + off);
#pragma unroll
                for (int mt = 0; mt < 4; mt++)
                    mmaf16(acc[mt][nt], af[mt][0].x, af[mt][1].x,
                           af[mt][0].y, af[mt][1].y, bf.x, bf.y);
            }
        }
        if (ch + 1 < NCHUNK) CP_WAIT0();
        __syncthreads();
    }

    const int n0 = bn * 128 + wn * 32 + 2 * c_;
    float bz[8];
#pragma unroll
    for (int nt = 0; nt < 4; nt++) {
        int n = n0 + 8 * nt;
        bz[2 * nt]     = (n     < VOCAB) ? bias[n]     : 0.f;
        bz[2 * nt + 1] = (n + 1 < VOCAB) ? bias[n + 1] : 0.f;
    }
    const int m0 = bm * 128 + wm * 64 + (lane >> 2);
#pragma unroll
    for (int mt = 0; mt < 4; mt++) {
        float* r0 = C + (size_t)(m0 + 16 * mt) * VOCAB;
        float* r1 = r0 + (size_t)8 * VOCAB;
#pragma unroll
        for (int nt = 0; nt < 4; nt++) {
            int n = n0 + 8 * nt;
            if (n < VOCAB) {
                r0[n] = acc[mt][nt][0] + bz[2 * nt];
                r1[n] = acc[mt][nt][2] + bz[2 * nt];
            }
            if (n + 1 < VOCAB) {
                r0[n + 1] = acc[mt][nt][1] + bz[2 * nt + 1];
                r1[n + 1] = acc[mt][nt][3] + bz[2 * nt + 1];
            }
        }
    }
}

// =====================================================================
// GRU gates (zero previous hidden state): h' = (1-z) * n   (layer 0)
// =====================================================================
__global__ void gru_gates(const float* __restrict__ gi, const float* __restrict__ bhh,
                          float* __restrict__ h, int ldh)
{
    int idx = blockIdx.x * blockDim.x + threadIdx.x;
    int b = idx >> 10, d = idx & 1023;
    const float* g = gi + (size_t)b * (3 * DIM);
    float r = 1.f / (1.f + expf(-(g[d]           + bhh[d])));
    float z = 1.f / (1.f + expf(-(g[DIM + d]     + bhh[DIM + d])));
    float n = tanhf(g[2 * DIM + d] + r * bhh[2 * DIM + d]);
    h[(size_t)b * ldh + d] = (1.f - z) * n;
}

// =====================================================================
// Fused attention (unchanged from R7): h1 gates in-block + online softmax.
// =====================================================================
#define ATTN_SMEM_BYTES ((1024 + 2 * 8 * 1024 + 8 + 512) * 4)

__global__ void __launch_bounds__(256)
attn_kernel(const float* __restrict__ enc, const int* __restrict__ mask,
            const float* __restrict__ gi, const float* __restrict__ bhh,
            float* __restrict__ cat)
{
    extern __shared__ float smf[];
    float* h1s   = smf;
    float* tiles = smf + 1024;
    float* wsh   = smf + 1024 + 16384;
    int*   msk   = (int*)(smf + 1024 + 16384 + 8);

    const int b   = blockIdx.x;
    const int tid = threadIdx.x;
    const float* encb  = enc  + (size_t)b * SEQ * DIM;
    const int*   maskb = mask + b * SEQ;

    msk[tid]       = maskb[tid];
    msk[tid + 256] = maskb[tid + 256];

    {
        const float* g = gi + (size_t)b * (3 * DIM);
        int d = tid * 4;
        float4 vr = *(const float4*)(g + d);
        float4 vz = *(const float4*)(g + DIM + d);
        float4 vn = *(const float4*)(g + 2 * DIM + d);
        float4 br = *(const float4*)(bhh + d);
        float4 bz = *(const float4*)(bhh + DIM + d);
        float4 bn = *(const float4*)(bhh + 2 * DIM + d);
        float h[4];
        float r0 = 1.f / (1.f + expf(-(vr.x + br.x)));
        float z0 = 1.f / (1.f + expf(-(vz.x + bz.x)));
        h[0] = (1.f - z0) * tanhf(vn.x + r0 * bn.x);
        float r1 = 1.f / (1.f + expf(-(vr.y + br.y)));
        float z1 = 1.f / (1.f + expf(-(vz.y + bz.y)));
        h[1] = (1.f - z1) * tanhf(vn.y + r1 * bn.y);
        float r2 = 1.f / (1.f + expf(-(vr.z + br.z)));
        float z2 = 1.f / (1.f + expf(-(vz.z + bz.z)));
        h[2] = (1.f - z2) * tanhf(vn.z + r2 * bn.z);
        float r3 = 1.f / (1.f + expf(-(vr.w + br.w)));
        float z3 = 1.f / (1.f + expf(-(vz.w + bz.w)));
        h[3] = (1.f - z3) * tanhf(vn.w + r3 * bn.w);
        float4 hv = make_float4(h[0], h[1], h[2], h[3]);
        *(float4*)(h1s + d) = hv;
        *(float4*)(cat + (size_t)b * (2 * DIM) + d) = hv;
    }

    const uint32_t tbase = (uint32_t)__cvta_generic_to_shared(tiles);
    auto issue = [&](int it) {
        const float* src = encb + (size_t)it * 8 * DIM + tid * 4;
        uint32_t dst = tbase + (uint32_t)((it & 1) * 32768 + tid * 16);
#pragma unroll
        for (int i = 0; i < 8; i++)
            CP_ASYNC16(dst + i * 4096, (const void*)(src + i * 1024));
    };

    issue(0); CP_COMMIT();
    issue(1); CP_COMMIT();

    float m = -1e30f, l = 0.f;
    float4 acc = make_float4(0.f, 0.f, 0.f, 0.f);

    for (int it = 0; it < SEQ / 8; it++) {
        CP_WAIT1();
        __syncthreads();
        const float* tb = tiles + (it & 1) * 8192;

        {
            int w = tid >> 5, lane = tid & 31;
            float p = 0.f;
            const float4* er = (const float4*)(tb + w * 1024);
            const float4* hr = (const float4*)h1s;
#pragma unroll
            for (int i = 0; i < 8; i++) {
                float4 e  = er[lane + i * 32];
                float4 hv = hr[lane + i * 32];
                p += e.x * hv.x + e.y * hv.y + e.z * hv.z + e.w * hv.w;
            }
#pragma unroll
            for (int off = 16; off; off >>= 1) p += __shfl_xor_sync(0xffffffffu, p, off);
            if (lane == 0) wsh[w] = msk[it * 8 + w] ? p : -1e30f;
        }
        __syncthreads();

        float wv[8];
        float tm = -1e30f;
#pragma unroll
        for (int j = 0; j < 8; j++) { wv[j] = wsh[j]; tm = fmaxf(tm, wv[j]); }
        float mnew  = fmaxf(m, tm);
        float scale = __expf(m - mnew);
        l *= scale;
        acc.x *= scale; acc.y *= scale; acc.z *= scale; acc.w *= scale;
#pragma unroll
        for (int j = 0; j < 8; j++) {
            float pj = __expf(wv[j] - mnew);
            l += pj;
            float4 e = *(const float4*)(tb + j * 1024 + tid * 4);
            acc.x += pj * e.x; acc.y += pj * e.y; acc.z += pj * e.z; acc.w += pj * e.w;
        }
        m = mnew;
        __syncthreads();

        if (it + 2 < SEQ / 8) issue(it + 2);
        CP_COMMIT();
    }

    float inv = 1.f / l;
    float4 o = make_float4(acc.x * inv, acc.y * inv, acc.z * inv, acc.w * inv);
    *(float4*)(cat + (size_t)b * (2 * DIM) + DIM + tid * 4) = o;
}

// =====================================================================
// launcher
// =====================================================================
extern "C" void kernel_launch(void* const* d_in, const int* in_sizes, int n_in,
                              void* d_out, int out_size)
{
    (void)in_sizes; (void)n_in; (void)out_size;
    const int*   tokens   = (const int*)  d_in[0];
    const float* enc      = (const float*)d_in[1];
    const int*   encmask  = (const int*)  d_in[2];
    const float* dec_emb  = (const float*)d_in[3];
    const float* Wih0     = (const float*)d_in[4];
    const float* bih0     = (const float*)d_in[6];
    const float* bhh0     = (const float*)d_in[7];
    const float* Wih1     = (const float*)d_in[8];
    const float* bih1     = (const float*)d_in[10];
    const float* bhh1     = (const float*)d_in[11];
    const float* preout_w = (const float*)d_in[12];
    const float* preout_b = (const float*)d_in[13];
    const float* out_w    = (const float*)d_in[14];
    const float* out_b    = (const float*)d_in[15];
    float* logits = (float*)d_out;

    float *gi, *h0, *cat, *pre;
    uint32_t* apack;
    cudaGetSymbolAddress((void**)&gi,    g_gi);
    cudaGetSymbolAddress((void**)&h0,    g_h0);
    cudaGetSymbolAddress((void**)&cat,   g_cat);
    cudaGetSymbolAddress((void**)&pre,   g_pre);
    cudaGetSymbolAddress((void**)&apack, g_Apack);

    static int smem_set = 0;
    if (!smem_set) {
        cudaFuncSetAttribute(logits_f16, cudaFuncAttributeMaxDynamicSharedMemorySize, LG_SMEM_BYTES);
        cudaFuncSetAttribute(gemm_f16<0>, cudaFuncAttributeMaxDynamicSharedMemorySize, LG_SMEM_BYTES);
        cudaFuncSetAttribute(gemm_f16<1>, cudaFuncAttributeMaxDynamicSharedMemorySize, LG_SMEM_BYTES);
        cudaFuncSetAttribute(attn_kernel, cudaFuncAttributeMaxDynamicSharedMemorySize, ATTN_SMEM_BYTES);
        smem_set = 1;
    }

    // 1) gi0 = dec_emb[tokens] @ Wih0[:, :D]^T + bih0   (fp16 MMA, gathered A)
    gemm_f16<0><<<2 * (3 * DIM / 128), 256, LG_SMEM_BYTES>>>(
        3 * DIM, DIM, dec_emb, DIM, tokens, Wih0, 2 * DIM, bih0, gi, 3 * DIM);

    // 2) h0
    gru_gates<<<(BATCH * DIM) / 256, 256>>>(gi, bhh0, h0, DIM);

    // 3) gi1 = h0 @ Wih1^T + bih1   (fp16 MMA)
    gemm_f16<0><<<2 * (3 * DIM / 128), 256, LG_SMEM_BYTES>>>(
        3 * DIM, DIM, h0, DIM, nullptr, Wih1, DIM, bih1, gi, 3 * DIM);

    // 4) fused: h1 gates + attention summary -> cat
    attn_kernel<<<BATCH, 256, ATTN_SMEM_BYTES>>>(enc, encmask, gi, bhh1, cat);

    // 5) pre = celu(cat @ preout_w^T + preout_b)   (fp16 MMA, celu epilogue)
    gemm_f16<1><<<2 * (DIM / 128), 256, LG_SMEM_BYTES>>>(
        DIM, 2 * DIM, cat, 2 * DIM, nullptr, preout_w, 2 * DIM, preout_b, pre, DIM);

    // 6) pack pre -> fp16 swizzled A for logits
    prepackA<<<32, 256>>>(pre, apack);

    // 7) logits = Apack @ out_w^T + out_b   (fp16 mma.sync, cp.async A)
    logits_f16<<<((VOCAB + 127) / 128) * 2, 256, LG_SMEM_BYTES>>>(apack, out_w, out_b, logits);
}